// round 1
// baseline (speedup 1.0000x reference)
#include <cuda_runtime.h>

typedef unsigned long long u64;

#define Bn 4
#define Ln 2048
#define Sn 2048
#define Hn 16
#define En 64
#define Dn 64
#define BM 128
#define BN 64
#define NT 128
#define QS_S 132   // Q^T [64][132]  (pad keeps 16B alignment + bank spread)
#define KS_S 68    // K^T [64][68]
#define VS_S 68    // V   [64][68]
#define PS_S 132   // P^T [64][132]
#define SMEM_FLOATS (En*QS_S + En*KS_S + BN*VS_S + BN*PS_S)  // 25600 floats = 100 KB

__device__ __forceinline__ u64 pack2(float lo, float hi) {
    u64 r; asm("mov.b64 %0, {%1,%2};" : "=l"(r) : "f"(lo), "f"(hi)); return r;
}
__device__ __forceinline__ void unpack2(u64 v, float& lo, float& hi) {
    asm("mov.b64 {%0,%1}, %2;" : "=f"(lo), "=f"(hi) : "l"(v));
}
__device__ __forceinline__ u64 fma2(u64 a, u64 b, u64 c) {
    u64 d; asm("fma.rn.f32x2 %0, %1, %2, %3;" : "=l"(d) : "l"(a), "l"(b), "l"(c)); return d;
}
__device__ __forceinline__ u64 mul2(u64 a, u64 b) {
    u64 d; asm("mul.rn.f32x2 %0, %1, %2;" : "=l"(d) : "l"(a), "l"(b)); return d;
}

extern __shared__ float smem[];

__global__ __launch_bounds__(NT, 2)
void fattn_kernel(const float* __restrict__ Q, const float* __restrict__ K,
                  const float* __restrict__ V, float* __restrict__ O)
{
    float* Qs = smem;              // [e][m] transposed
    float* Ks = Qs + En * QS_S;    // [e][n] transposed
    float* Vs = Ks + En * KS_S;    // [n][d]
    float* Ps = Vs + BN * VS_S;    // [n][m] transposed

    const int tid = threadIdx.x;
    const int ty = tid >> 3, tx = tid & 7;
    const int m0 = ty * 8;     // 8 query rows per thread
    const int c0 = tx * 8;     // 8 cols (n for QK, d for PV)

    const int bh = blockIdx.y;
    const int b = bh >> 4, h = bh & 15;
    const int mbase = blockIdx.x * BM;

    // element layouts: [B, L, H, E] etc.; row stride = H*E = 1024
    const float* Qg = Q + (size_t)b * Ln * Hn * En + (size_t)h * En + (size_t)mbase * Hn * En;
    const float* Kg = K + (size_t)b * Sn * Hn * En + (size_t)h * En;
    const float* Vg = V + (size_t)b * Sn * Hn * Dn + (size_t)h * Dn;
    float*       Og = O + (size_t)b * Ln * Hn * Dn + (size_t)h * Dn + (size_t)mbase * Hn * Dn;

    // ---- load Q tile, transposed into smem (once per CTA) ----
    #pragma unroll
    for (int i = 0; i < 16; ++i) {
        int lin = tid + i * NT;          // 0..2047
        int m = lin >> 4;
        int e4 = (lin & 15) * 4;
        float4 q = *(const float4*)(Qg + m * 1024 + e4);
        Qs[(e4 + 0) * QS_S + m] = q.x;
        Qs[(e4 + 1) * QS_S + m] = q.y;
        Qs[(e4 + 2) * QS_S + m] = q.z;
        Qs[(e4 + 3) * QS_S + m] = q.w;
    }

    u64 accO[4][8];
    #pragma unroll
    for (int i = 0; i < 4; ++i)
        #pragma unroll
        for (int j = 0; j < 8; ++j) accO[i][j] = 0ull;  // bits == (0.f,0.f)

    float mrow[8], lrow[8];
    #pragma unroll
    for (int r = 0; r < 8; ++r) { mrow[r] = -1e30f; lrow[r] = 0.f; }

    for (int nb = 0; nb < Sn; nb += BN) {
        // ---- load K^T and V tiles ----
        #pragma unroll
        for (int i = 0; i < 8; ++i) {
            int lin = tid + i * NT;      // 0..1023
            int n = lin >> 4;
            int e4 = (lin & 15) * 4;
            float4 kq = *(const float4*)(Kg + (nb + n) * 1024 + e4);
            Ks[(e4 + 0) * KS_S + n] = kq.x;
            Ks[(e4 + 1) * KS_S + n] = kq.y;
            Ks[(e4 + 2) * KS_S + n] = kq.z;
            Ks[(e4 + 3) * KS_S + n] = kq.w;
            float4 vv = *(const float4*)(Vg + (nb + n) * 1024 + e4);
            *(float4*)(Vs + n * VS_S + e4) = vv;
        }
        __syncthreads();

        // ---- S = Q @ K^T (packed f32x2, m-paired accumulators) ----
        u64 accS[4][8];
        #pragma unroll
        for (int i = 0; i < 4; ++i)
            #pragma unroll
            for (int j = 0; j < 8; ++j) accS[i][j] = 0ull;

        #pragma unroll 4
        for (int k = 0; k < En; ++k) {
            const float* qk = Qs + k * QS_S + m0;
            ulonglong2 A0 = *(const ulonglong2*)(qk);
            ulonglong2 A1 = *(const ulonglong2*)(qk + 4);
            const float* kk = Ks + k * KS_S + c0;
            float4 b0 = *(const float4*)(kk);
            float4 b1 = *(const float4*)(kk + 4);
            u64 am[4] = {A0.x, A0.y, A1.x, A1.y};
            u64 bb[8] = {pack2(b0.x, b0.x), pack2(b0.y, b0.y), pack2(b0.z, b0.z), pack2(b0.w, b0.w),
                         pack2(b1.x, b1.x), pack2(b1.y, b1.y), pack2(b1.z, b1.z), pack2(b1.w, b1.w)};
            #pragma unroll
            for (int mp = 0; mp < 4; ++mp)
                #pragma unroll
                for (int n = 0; n < 8; ++n)
                    accS[mp][n] = fma2(am[mp], bb[n], accS[mp][n]);
        }

        // ---- online softmax (rows split across 8 tx lanes) ----
        #pragma unroll
        for (int mp = 0; mp < 4; ++mp) {
            float lo[8], hi[8];
            #pragma unroll
            for (int n = 0; n < 8; ++n) unpack2(accS[mp][n], lo[n], hi[n]);
            float mx0 = lo[0], mx1 = hi[0];
            #pragma unroll
            for (int n = 1; n < 8; ++n) { mx0 = fmaxf(mx0, lo[n]); mx1 = fmaxf(mx1, hi[n]); }
            #pragma unroll
            for (int off = 1; off < 8; off <<= 1) {
                mx0 = fmaxf(mx0, __shfl_xor_sync(0xffffffffu, mx0, off));
                mx1 = fmaxf(mx1, __shfl_xor_sync(0xffffffffu, mx1, off));
            }
            float nm0 = fmaxf(mrow[2 * mp],     mx0);
            float nm1 = fmaxf(mrow[2 * mp + 1], mx1);
            float s0 = 0.f, s1 = 0.f;
            #pragma unroll
            for (int n = 0; n < 8; ++n) {
                lo[n] = __expf(lo[n] - nm0); s0 += lo[n];
                hi[n] = __expf(hi[n] - nm1); s1 += hi[n];
            }
            #pragma unroll
            for (int off = 1; off < 8; off <<= 1) {
                s0 += __shfl_xor_sync(0xffffffffu, s0, off);
                s1 += __shfl_xor_sync(0xffffffffu, s1, off);
            }
            float al0 = __expf(mrow[2 * mp]     - nm0);
            float al1 = __expf(mrow[2 * mp + 1] - nm1);
            lrow[2 * mp]     = lrow[2 * mp]     * al0 + s0;
            lrow[2 * mp + 1] = lrow[2 * mp + 1] * al1 + s1;
            mrow[2 * mp] = nm0; mrow[2 * mp + 1] = nm1;
            u64 ap = pack2(al0, al1);
            #pragma unroll
            for (int dn = 0; dn < 8; ++dn) accO[mp][dn] = mul2(accO[mp][dn], ap);
            // write P transposed: P^T[n][m0+2mp .. m0+2mp+1]
            #pragma unroll
            for (int n = 0; n < 8; ++n)
                *(float2*)(Ps + (c0 + n) * PS_S + m0 + 2 * mp) = make_float2(lo[n], hi[n]);
        }
        __syncthreads();

        // ---- O += P @ V (packed f32x2) ----
        #pragma unroll 4
        for (int k = 0; k < BN; ++k) {
            const float* pk = Ps + k * PS_S + m0;
            ulonglong2 A0 = *(const ulonglong2*)(pk);
            ulonglong2 A1 = *(const ulonglong2*)(pk + 4);
            const float* vk = Vs + k * VS_S + c0;
            float4 b0 = *(const float4*)(vk);
            float4 b1 = *(const float4*)(vk + 4);
            u64 am[4] = {A0.x, A0.y, A1.x, A1.y};
            u64 bb[8] = {pack2(b0.x, b0.x), pack2(b0.y, b0.y), pack2(b0.z, b0.z), pack2(b0.w, b0.w),
                         pack2(b1.x, b1.x), pack2(b1.y, b1.y), pack2(b1.z, b1.z), pack2(b1.w, b1.w)};
            #pragma unroll
            for (int mp = 0; mp < 4; ++mp)
                #pragma unroll
                for (int n = 0; n < 8; ++n)
                    accO[mp][n] = fma2(am[mp], bb[n], accO[mp][n]);
        }
        __syncthreads();
    }

    // ---- epilogue: divide by l, write out ----
    #pragma unroll
    for (int mp = 0; mp < 4; ++mp) {
        float inv0 = 1.f / lrow[2 * mp];
        float inv1 = 1.f / lrow[2 * mp + 1];
        float o0[8], o1[8];
        #pragma unroll
        for (int dn = 0; dn < 8; ++dn) {
            float a, c; unpack2(accO[mp][dn], a, c);
            o0[dn] = a * inv0; o1[dn] = c * inv1;
        }
        float* r0 = Og + (m0 + 2 * mp) * 1024 + c0;
        float* r1 = r0 + 1024;
        *(float4*)(r0)     = make_float4(o0[0], o0[1], o0[2], o0[3]);
        *(float4*)(r0 + 4) = make_float4(o0[4], o0[5], o0[6], o0[7]);
        *(float4*)(r1)     = make_float4(o1[0], o1[1], o1[2], o1[3]);
        *(float4*)(r1 + 4) = make_float4(o1[4], o1[5], o1[6], o1[7]);
    }
}

extern "C" void kernel_launch(void* const* d_in, const int* in_sizes, int n_in,
                              void* d_out, int out_size)
{
    const float* Q = (const float*)d_in[0];
    const float* K = (const float*)d_in[1];
    const float* V = (const float*)d_in[2];
    float* O = (float*)d_out;

    const int smem_bytes = SMEM_FLOATS * (int)sizeof(float);   // 102400
    cudaFuncSetAttribute(fattn_kernel, cudaFuncAttributeMaxDynamicSharedMemorySize, smem_bytes);

    dim3 grid(Ln / BM, Bn * Hn);   // (16, 64)
    fattn_kernel<<<grid, NT, smem_bytes>>>(Q, K, V, O);
}

// round 3
// speedup vs baseline: 2.8508x; 2.8508x over previous
#include <cuda_runtime.h>
#include <cuda_bf16.h>
#include <cstdint>

typedef unsigned int u32;

#define Bn 4
#define Ln 2048
#define Sn 2048
#define Hn 16
#define En 64
#define Dn 64
#define BM 128
#define BN 128
#define NT 256
#define NTILES (Sn / BN)

// pitch: 64 bf16 data + 8 pad = 72 bf16 = 144 bytes (conflict-free ldmatrix)
#define PITCH 144
#define TILE_BYTES (128 * PITCH)          // 18432 per array
#define OFF_QH 0
#define OFF_QL (OFF_QH + TILE_BYTES)
#define OFF_KV(buf) (2 * TILE_BYTES + (buf) * 4 * TILE_BYTES)
// within a KV buffer: KH, KL, VH, VL
#define SMEM_BYTES (2 * TILE_BYTES + 2 * 4 * TILE_BYTES)   // 184320

// ---------------- scratch (bf16 hi/lo split, [b,h,s,e]) ----------------
__device__ __nv_bfloat16 g_Qhi[(size_t)Bn * Hn * Ln * En];
__device__ __nv_bfloat16 g_Qlo[(size_t)Bn * Hn * Ln * En];
__device__ __nv_bfloat16 g_Khi[(size_t)Bn * Hn * Sn * En];
__device__ __nv_bfloat16 g_Klo[(size_t)Bn * Hn * Sn * En];
__device__ __nv_bfloat16 g_Vhi[(size_t)Bn * Hn * Sn * Dn];
__device__ __nv_bfloat16 g_Vlo[(size_t)Bn * Hn * Sn * Dn];

// ---------------- helpers ----------------
__device__ __forceinline__ u32 smem_u32(const void* p) {
    u32 a;
    asm("{ .reg .u64 t; cvta.to.shared.u64 t, %1; cvt.u32.u64 %0, t; }" : "=r"(a) : "l"(p));
    return a;
}
__device__ __forceinline__ void cpa16(u32 dst, const void* src) {
    asm volatile("cp.async.cg.shared.global [%0], [%1], 16;" :: "r"(dst), "l"(src));
}
__device__ __forceinline__ void cpa_commit() {
    asm volatile("cp.async.commit_group;" ::: "memory");
}
template <int N>
__device__ __forceinline__ void cpa_wait() {
    asm volatile("cp.async.wait_group %0;" :: "n"(N) : "memory");
}
__device__ __forceinline__ void ldsm_x4(u32* r, u32 addr) {
    asm volatile("ldmatrix.sync.aligned.m8n8.x4.shared.b16 {%0,%1,%2,%3}, [%4];"
                 : "=r"(r[0]), "=r"(r[1]), "=r"(r[2]), "=r"(r[3]) : "r"(addr));
}
__device__ __forceinline__ void ldsm_x4_t(u32* r, u32 addr) {
    asm volatile("ldmatrix.sync.aligned.m8n8.x4.trans.shared.b16 {%0,%1,%2,%3}, [%4];"
                 : "=r"(r[0]), "=r"(r[1]), "=r"(r[2]), "=r"(r[3]) : "r"(addr));
}
__device__ __forceinline__ void mma_bf16(float* c, const u32* a, u32 b0, u32 b1) {
    asm volatile(
        "mma.sync.aligned.m16n8k16.row.col.f32.bf16.bf16.f32 "
        "{%0,%1,%2,%3}, {%4,%5,%6,%7}, {%8,%9}, {%0,%1,%2,%3};"
        : "+f"(c[0]), "+f"(c[1]), "+f"(c[2]), "+f"(c[3])
        : "r"(a[0]), "r"(a[1]), "r"(a[2]), "r"(a[3]), "r"(b0), "r"(b1));
}
__device__ __forceinline__ void split_pack(float x0, float x1, u32& hi, u32& lo) {
    __nv_bfloat16 h0 = __float2bfloat16(x0), h1 = __float2bfloat16(x1);
    float l0 = x0 - __bfloat162float(h0);
    float l1 = x1 - __bfloat162float(h1);
    __nv_bfloat162 hh = __halves2bfloat162(h0, h1);   // .x = low half = k-element 0
    __nv_bfloat162 ll = __halves2bfloat162(__float2bfloat16(l0), __float2bfloat16(l1));
    hi = *(u32*)&hh;
    lo = *(u32*)&ll;
}

// ---------------- pre-pass: split+permute [b,x,h,e] -> [b,h,x,e] hi/lo ----------------
__global__ void pack_split(const float* __restrict__ src, __nv_bfloat16* __restrict__ hi,
                           __nv_bfloat16* __restrict__ lo) {
    int i4 = blockIdx.x * 256 + threadIdx.x;       // 0..8388607 float4s
    size_t lin = (size_t)i4 * 4;
    int e = lin & 63;
    int h = (lin >> 6) & 15;
    int l = (lin >> 10) & 2047;
    int b = (int)(lin >> 21);
    float4 v = ((const float4*)src)[i4];
    size_t dst = ((((size_t)b * Hn + h) * Ln + l) * En) + e;
    float x[4] = {v.x, v.y, v.z, v.w};
    __nv_bfloat16 hh[4], ll[4];
#pragma unroll
    for (int j = 0; j < 4; ++j) {
        hh[j] = __float2bfloat16(x[j]);
        ll[j] = __float2bfloat16(x[j] - __bfloat162float(hh[j]));
    }
    *(uint2*)(hi + dst) = *(uint2*)hh;
    *(uint2*)(lo + dst) = *(uint2*)ll;
}

// ---------------- main attention kernel ----------------
extern __shared__ char dsm[];

__global__ __launch_bounds__(NT, 1)
void fattn_mma(float* __restrict__ O) {
    const u32 sb = smem_u32(dsm);
    const int tid = threadIdx.x;
    const int w = tid >> 5;
    const int lane = tid & 31;

    const int bh = blockIdx.y;
    const int b = bh >> 4, h = bh & 15;
    const int mbase = blockIdx.x * BM;

    const __nv_bfloat16* gq_h = g_Qhi + ((size_t)bh * Ln + mbase) * En;
    const __nv_bfloat16* gq_l = g_Qlo + ((size_t)bh * Ln + mbase) * En;
    const __nv_bfloat16* gk_h = g_Khi + (size_t)bh * Sn * En;
    const __nv_bfloat16* gk_l = g_Klo + (size_t)bh * Sn * En;
    const __nv_bfloat16* gv_h = g_Vhi + (size_t)bh * Sn * Dn;
    const __nv_bfloat16* gv_l = g_Vlo + (size_t)bh * Sn * Dn;

    // per-thread cooperative-load slots: 4 uint4 per array
    int ldr[4], ldc[4];
#pragma unroll
    for (int i = 0; i < 4; ++i) {
        int idx = tid + i * NT;     // 0..1023
        ldr[i] = idx >> 3;
        ldc[i] = idx & 7;
    }

    // prologue: Q + tile0 as one cp.async group
#pragma unroll
    for (int i = 0; i < 4; ++i) {
        int idx = tid + i * NT;
        u32 d = sb + ldr[i] * PITCH + ldc[i] * 16;
        cpa16(d + OFF_QH, (const char*)gq_h + idx * 16);
        cpa16(d + OFF_QL, (const char*)gq_l + idx * 16);
        cpa16(d + OFF_KV(0) + 0 * TILE_BYTES, (const char*)gk_h + idx * 16);
        cpa16(d + OFF_KV(0) + 1 * TILE_BYTES, (const char*)gk_l + idx * 16);
        cpa16(d + OFF_KV(0) + 2 * TILE_BYTES, (const char*)gv_h + idx * 16);
        cpa16(d + OFF_KV(0) + 3 * TILE_BYTES, (const char*)gv_l + idx * 16);
    }
    cpa_commit();

    // ldmatrix per-lane offsets
    const u32 koff = (lane & 7) * PITCH + (lane >> 3) * 16;                 // K (no-trans)
    const u32 qoff = (16 * w + ((lane >> 3) & 1) * 8 + (lane & 7)) * PITCH + (lane >> 4) * 16;
    const u32 voff = (((lane >> 3) & 1) * 8 + (lane & 7)) * PITCH + (lane >> 4) * 16;   // V (trans)

    u32 Qh[4][4], Ql[4][4];
    float accO[8][4];
#pragma unroll
    for (int j = 0; j < 8; ++j)
#pragma unroll
        for (int i = 0; i < 4; ++i) accO[j][i] = 0.f;
    float lp0 = 0.f, lp1 = 0.f;

    for (int t = 0; t < NTILES; ++t) {
        const u32 kvb = sb + OFF_KV(t & 1);

        __syncthreads();   // prev compute done -> other buffer free
        if (t + 1 < NTILES) {
            const u32 nb = sb + OFF_KV((t + 1) & 1);
            const size_t goff = (size_t)(t + 1) * BN * En;
#pragma unroll
            for (int i = 0; i < 4; ++i) {
                int idx = tid + i * NT;
                u32 d = nb + ldr[i] * PITCH + ldc[i] * 16;
                cpa16(d + 0 * TILE_BYTES, (const char*)(gk_h + goff) + idx * 16);
                cpa16(d + 1 * TILE_BYTES, (const char*)(gk_l + goff) + idx * 16);
                cpa16(d + 2 * TILE_BYTES, (const char*)(gv_h + goff) + idx * 16);
                cpa16(d + 3 * TILE_BYTES, (const char*)(gv_l + goff) + idx * 16);
            }
            cpa_commit();
            cpa_wait<1>();
        } else {
            cpa_wait<0>();
        }
        __syncthreads();

        if (t == 0) {
            // load persistent Q fragments
#pragma unroll
            for (int k = 0; k < 4; ++k) {
                ldsm_x4(Qh[k], sb + OFF_QH + k * 32 + qoff);
                ldsm_x4(Ql[k], sb + OFF_QL + k * 32 + qoff);
            }
        }

        // ---- S = Qhi*Khi + Qhi*Klo + Qlo*Khi ----
        float accS[16][4];
#pragma unroll
        for (int j = 0; j < 16; ++j)
#pragma unroll
            for (int i = 0; i < 4; ++i) accS[j][i] = 0.f;

#pragma unroll
        for (int hh = 0; hh < 2; ++hh) {
#pragma unroll
            for (int j = 0; j < 16; ++j) {
                u32 kh[4], kl[4];
                ldsm_x4(kh, kvb + 0 * TILE_BYTES + j * (8 * PITCH) + hh * 64 + koff);
                ldsm_x4(kl, kvb + 1 * TILE_BYTES + j * (8 * PITCH) + hh * 64 + koff);
                mma_bf16(accS[j], Qh[2 * hh], kh[0], kh[1]);
                mma_bf16(accS[j], Qh[2 * hh], kl[0], kl[1]);
                mma_bf16(accS[j], Ql[2 * hh], kh[0], kh[1]);
                mma_bf16(accS[j], Qh[2 * hh + 1], kh[2], kh[3]);
                mma_bf16(accS[j], Qh[2 * hh + 1], kl[2], kl[3]);
                mma_bf16(accS[j], Ql[2 * hh + 1], kh[2], kh[3]);
            }
        }

        // ---- softmax (fixed shift, no max pass) ----
#pragma unroll
        for (int j = 0; j < 16; ++j) {
            float p0 = __expf(accS[j][0] - 30.f);
            float p1 = __expf(accS[j][1] - 30.f);
            float p2 = __expf(accS[j][2] - 30.f);
            float p3 = __expf(accS[j][3] - 30.f);
            accS[j][0] = p0; accS[j][1] = p1; accS[j][2] = p2; accS[j][3] = p3;
            lp0 += p0 + p1;
            lp1 += p2 + p3;
        }

        // ---- O += Phi*Vhi + Phi*Vlo + Plo*Vhi ----
#pragma unroll
        for (int kt = 0; kt < 8; ++kt) {
            u32 ah[4], al[4];
            split_pack(accS[2 * kt][0],     accS[2 * kt][1],     ah[0], al[0]);
            split_pack(accS[2 * kt][2],     accS[2 * kt][3],     ah[1], al[1]);
            split_pack(accS[2 * kt + 1][0], accS[2 * kt + 1][1], ah[2], al[2]);
            split_pack(accS[2 * kt + 1][2], accS[2 * kt + 1][3], ah[3], al[3]);
#pragma unroll
            for (int q = 0; q < 4; ++q) {
                u32 vh[4], vl[4];
                ldsm_x4_t(vh, kvb + 2 * TILE_BYTES + kt * (16 * PITCH) + q * 32 + voff);
                ldsm_x4_t(vl, kvb + 3 * TILE_BYTES + kt * (16 * PITCH) + q * 32 + voff);
                mma_bf16(accO[2 * q], ah, vh[0], vh[1]);
                mma_bf16(accO[2 * q], ah, vl[0], vl[1]);
                mma_bf16(accO[2 * q], al, vh[0], vh[1]);
                mma_bf16(accO[2 * q + 1], ah, vh[2], vh[3]);
                mma_bf16(accO[2 * q + 1], ah, vl[2], vl[3]);
                mma_bf16(accO[2 * q + 1], al, vh[2], vh[3]);
            }
        }
    }

    // ---- epilogue: reduce l across the 4 lanes of each row group, scale, store ----
    lp0 += __shfl_xor_sync(0xffffffffu, lp0, 1);
    lp0 += __shfl_xor_sync(0xffffffffu, lp0, 2);
    lp1 += __shfl_xor_sync(0xffffffffu, lp1, 1);
    lp1 += __shfl_xor_sync(0xffffffffu, lp1, 2);
    const float inv0 = 1.f / lp0;
    const float inv1 = 1.f / lp1;

    const int row0 = mbase + 16 * w + (lane >> 2);
    float* o0 = O + (((size_t)b * Ln + row0) * Hn + h) * Dn + (lane & 3) * 2;
    float* o1 = o0 + (size_t)8 * Hn * Dn;
#pragma unroll
    for (int j = 0; j < 8; ++j) {
        *(float2*)(o0 + 8 * j) = make_float2(accO[j][0] * inv0, accO[j][1] * inv0);
        *(float2*)(o1 + 8 * j) = make_float2(accO[j][2] * inv1, accO[j][3] * inv1);
    }
}

// ---------------- launch ----------------
extern "C" void kernel_launch(void* const* d_in, const int* in_sizes, int n_in,
                              void* d_out, int out_size) {
    const float* Q = (const float*)d_in[0];
    const float* K = (const float*)d_in[1];
    const float* V = (const float*)d_in[2];
    float* O = (float*)d_out;

    __nv_bfloat16 *qh, *ql, *kh, *kl, *vh, *vl;
    cudaGetSymbolAddress((void**)&qh, g_Qhi);
    cudaGetSymbolAddress((void**)&ql, g_Qlo);
    cudaGetSymbolAddress((void**)&kh, g_Khi);
    cudaGetSymbolAddress((void**)&kl, g_Klo);
    cudaGetSymbolAddress((void**)&vh, g_Vhi);
    cudaGetSymbolAddress((void**)&vl, g_Vlo);

    pack_split<<<8192, 256>>>(Q, qh, ql);
    pack_split<<<8192, 256>>>(K, kh, kl);
    pack_split<<<8192, 256>>>(V, vh, vl);

    static int configured = 0;
    cudaFuncSetAttribute(fattn_mma, cudaFuncAttributeMaxDynamicSharedMemorySize, SMEM_BYTES);
    (void)configured;

    fattn_mma<<<dim3(Ln / BM, Bn * Hn), NT, SMEM_BYTES>>>(O);
}

// round 4
// speedup vs baseline: 3.6134x; 1.2675x over previous
#include <cuda_runtime.h>
#include <cuda_bf16.h>
#include <cuda_fp16.h>
#include <cstdint>

typedef unsigned int u32;

#define Bn 4
#define Ln 2048
#define Sn 2048
#define Hn 16
#define En 64
#define Dn 64
#define BM 128
#define BN 128
#define NT 256
#define NTILES (Sn / BN)

// pitch: 64 elems * 2B + 16B pad = 144 bytes (conflict-free ldmatrix)
#define PITCH 144
#define TILE_BYTES (128 * PITCH)          // 18432 per array
#define OFF_QH 0
#define OFF_QL (OFF_QH + TILE_BYTES)
// per KV buffer: KH(bf16), KL(bf16), VF(fp16)
#define OFF_KV(buf) (2 * TILE_BYTES + (buf) * 3 * TILE_BYTES)
#define SMEM_BYTES (2 * TILE_BYTES + 2 * 3 * TILE_BYTES)   // 147456

// ---------------- scratch ----------------
__device__ __nv_bfloat16 g_Qhi[(size_t)Bn * Hn * Ln * En];
__device__ __nv_bfloat16 g_Qlo[(size_t)Bn * Hn * Ln * En];
__device__ __nv_bfloat16 g_Khi[(size_t)Bn * Hn * Sn * En];
__device__ __nv_bfloat16 g_Klo[(size_t)Bn * Hn * Sn * En];
__device__ __half        g_Vf [(size_t)Bn * Hn * Sn * Dn];   // [b,h,s,d] fp16

// ---------------- helpers ----------------
__device__ __forceinline__ u32 smem_u32(const void* p) {
    u32 a;
    asm("{ .reg .u64 t; cvta.to.shared.u64 t, %1; cvt.u32.u64 %0, t; }" : "=r"(a) : "l"(p));
    return a;
}
__device__ __forceinline__ void cpa16(u32 dst, const void* src) {
    asm volatile("cp.async.cg.shared.global [%0], [%1], 16;" :: "r"(dst), "l"(src));
}
__device__ __forceinline__ void cpa_commit() {
    asm volatile("cp.async.commit_group;" ::: "memory");
}
template <int N>
__device__ __forceinline__ void cpa_wait() {
    asm volatile("cp.async.wait_group %0;" :: "n"(N) : "memory");
}
__device__ __forceinline__ void ldsm_x4(u32* r, u32 addr) {
    asm volatile("ldmatrix.sync.aligned.m8n8.x4.shared.b16 {%0,%1,%2,%3}, [%4];"
                 : "=r"(r[0]), "=r"(r[1]), "=r"(r[2]), "=r"(r[3]) : "r"(addr));
}
__device__ __forceinline__ void ldsm_x4_t(u32* r, u32 addr) {
    asm volatile("ldmatrix.sync.aligned.m8n8.x4.trans.shared.b16 {%0,%1,%2,%3}, [%4];"
                 : "=r"(r[0]), "=r"(r[1]), "=r"(r[2]), "=r"(r[3]) : "r"(addr));
}
__device__ __forceinline__ void mma_bf16(float* c, const u32* a, u32 b0, u32 b1) {
    asm volatile(
        "mma.sync.aligned.m16n8k16.row.col.f32.bf16.bf16.f32 "
        "{%0,%1,%2,%3}, {%4,%5,%6,%7}, {%8,%9}, {%0,%1,%2,%3};"
        : "+f"(c[0]), "+f"(c[1]), "+f"(c[2]), "+f"(c[3])
        : "r"(a[0]), "r"(a[1]), "r"(a[2]), "r"(a[3]), "r"(b0), "r"(b1));
}
__device__ __forceinline__ void mma_fp16(float* c, const u32* a, u32 b0, u32 b1) {
    asm volatile(
        "mma.sync.aligned.m16n8k16.row.col.f32.f16.f16.f32 "
        "{%0,%1,%2,%3}, {%4,%5,%6,%7}, {%8,%9}, {%0,%1,%2,%3};"
        : "+f"(c[0]), "+f"(c[1]), "+f"(c[2]), "+f"(c[3])
        : "r"(a[0]), "r"(a[1]), "r"(a[2]), "r"(a[3]), "r"(b0), "r"(b1));
}
__device__ __forceinline__ u32 h2pack(float x0, float x1) {
    __half2 h = __floats2half2_rn(x0, x1);   // .x = low half = k-element 0
    return *(u32*)&h;
}

// ---------------- pre-pass: split+permute Q/K [b,x,h,e] -> [b,h,x,e] hi/lo ----------------
__global__ void pack_split(const float* __restrict__ src, __nv_bfloat16* __restrict__ hi,
                           __nv_bfloat16* __restrict__ lo) {
    int i4 = blockIdx.x * 256 + threadIdx.x;
    size_t lin = (size_t)i4 * 4;
    int e = lin & 63;
    int h = (lin >> 6) & 15;
    int l = (lin >> 10) & 2047;
    int b = (int)(lin >> 21);
    float4 v = ((const float4*)src)[i4];
    size_t dst = ((((size_t)b * Hn + h) * Ln + l) * En) + e;
    float x[4] = {v.x, v.y, v.z, v.w};
    __nv_bfloat16 hh[4], ll[4];
#pragma unroll
    for (int j = 0; j < 4; ++j) {
        hh[j] = __float2bfloat16(x[j]);
        ll[j] = __float2bfloat16(x[j] - __bfloat162float(hh[j]));
    }
    *(uint2*)(hi + dst) = *(uint2*)hh;
    *(uint2*)(lo + dst) = *(uint2*)ll;
}

// ---------------- pre-pass: V [b,s,h,d] -> [b,h,s,d] fp16 ----------------
__global__ void pack_v(const float* __restrict__ src, __half* __restrict__ dst) {
    int i4 = blockIdx.x * 256 + threadIdx.x;
    size_t lin = (size_t)i4 * 4;
    int d = lin & 63;
    int h = (lin >> 6) & 15;
    int s = (lin >> 10) & 2047;
    int b = (int)(lin >> 21);
    float4 v = ((const float4*)src)[i4];
    __half hh[4] = {__float2half_rn(v.x), __float2half_rn(v.y),
                    __float2half_rn(v.z), __float2half_rn(v.w)};
    size_t o = ((((size_t)b * Hn + h) * Sn + s) * Dn) + d;
    *(uint2*)(dst + o) = *(uint2*)hh;
}

// ---------------- main attention kernel ----------------
extern __shared__ char dsm[];

__global__ __launch_bounds__(NT, 1)
void fattn_mma(float* __restrict__ O) {
    const u32 sb = smem_u32(dsm);
    const int tid = threadIdx.x;
    const int w = tid >> 5;
    const int lane = tid & 31;

    const int bh = blockIdx.y;
    const int b = bh >> 4, h = bh & 15;
    const int mbase = blockIdx.x * BM;

    const __nv_bfloat16* gq_h = g_Qhi + ((size_t)bh * Ln + mbase) * En;
    const __nv_bfloat16* gq_l = g_Qlo + ((size_t)bh * Ln + mbase) * En;
    const __nv_bfloat16* gk_h = g_Khi + (size_t)bh * Sn * En;
    const __nv_bfloat16* gk_l = g_Klo + (size_t)bh * Sn * En;
    const __half*        gv   = g_Vf  + (size_t)bh * Sn * Dn;

    int ldr[4], ldc[4];
#pragma unroll
    for (int i = 0; i < 4; ++i) {
        int idx = tid + i * NT;
        ldr[i] = idx >> 3;
        ldc[i] = idx & 7;
    }

    // prologue: Q + tile0
#pragma unroll
    for (int i = 0; i < 4; ++i) {
        int idx = tid + i * NT;
        u32 d = sb + ldr[i] * PITCH + ldc[i] * 16;
        cpa16(d + OFF_QH, (const char*)gq_h + idx * 16);
        cpa16(d + OFF_QL, (const char*)gq_l + idx * 16);
        cpa16(d + OFF_KV(0) + 0 * TILE_BYTES, (const char*)gk_h + idx * 16);
        cpa16(d + OFF_KV(0) + 1 * TILE_BYTES, (const char*)gk_l + idx * 16);
        cpa16(d + OFF_KV(0) + 2 * TILE_BYTES, (const char*)gv   + idx * 16);
    }
    cpa_commit();

    const u32 koff = (lane & 7) * PITCH + (lane >> 3) * 16;
    const u32 qoff = (16 * w + ((lane >> 3) & 1) * 8 + (lane & 7)) * PITCH + (lane >> 4) * 16;
    const u32 voff = (((lane >> 3) & 1) * 8 + (lane & 7)) * PITCH + (lane >> 4) * 16;

    u32 Qh[4][4], Ql[4][4];
    float accO[8][4];
#pragma unroll
    for (int j = 0; j < 8; ++j)
#pragma unroll
        for (int i = 0; i < 4; ++i) accO[j][i] = 0.f;
    float lp0 = 0.f, lp1 = 0.f;
    float m0 = -1e30f, m1 = -1e30f;   // running row maxima

    for (int t = 0; t < NTILES; ++t) {
        const u32 kvb = sb + OFF_KV(t & 1);

        __syncthreads();
        if (t + 1 < NTILES) {
            const u32 nb = sb + OFF_KV((t + 1) & 1);
            const size_t goffK = (size_t)(t + 1) * BN * En;
            const size_t goffV = (size_t)(t + 1) * BN * Dn;
#pragma unroll
            for (int i = 0; i < 4; ++i) {
                int idx = tid + i * NT;
                u32 d = nb + ldr[i] * PITCH + ldc[i] * 16;
                cpa16(d + 0 * TILE_BYTES, (const char*)(gk_h + goffK) + idx * 16);
                cpa16(d + 1 * TILE_BYTES, (const char*)(gk_l + goffK) + idx * 16);
                cpa16(d + 2 * TILE_BYTES, (const char*)(gv + goffV) + idx * 16);
            }
            cpa_commit();
            cpa_wait<1>();
        } else {
            cpa_wait<0>();
        }
        __syncthreads();

        if (t == 0) {
#pragma unroll
            for (int k = 0; k < 4; ++k) {
                ldsm_x4(Qh[k], sb + OFF_QH + k * 32 + qoff);
                ldsm_x4(Ql[k], sb + OFF_QL + k * 32 + qoff);
            }
        }

        // ---- S = Qhi*Khi + Qhi*Klo + Qlo*Khi (bf16 3-term) ----
        float accS[16][4];
#pragma unroll
        for (int j = 0; j < 16; ++j)
#pragma unroll
            for (int i = 0; i < 4; ++i) accS[j][i] = 0.f;

#pragma unroll
        for (int hh = 0; hh < 2; ++hh) {
#pragma unroll
            for (int j = 0; j < 16; ++j) {
                u32 kh[4], kl[4];
                ldsm_x4(kh, kvb + 0 * TILE_BYTES + j * (8 * PITCH) + hh * 64 + koff);
                ldsm_x4(kl, kvb + 1 * TILE_BYTES + j * (8 * PITCH) + hh * 64 + koff);
                mma_bf16(accS[j], Qh[2 * hh], kh[0], kh[1]);
                mma_bf16(accS[j], Qh[2 * hh], kl[0], kl[1]);
                mma_bf16(accS[j], Ql[2 * hh], kh[0], kh[1]);
                mma_bf16(accS[j], Qh[2 * hh + 1], kh[2], kh[3]);
                mma_bf16(accS[j], Qh[2 * hh + 1], kl[2], kl[3]);
                mma_bf16(accS[j], Ql[2 * hh + 1], kh[2], kh[3]);
            }
        }

        // ---- online softmax: tile row max, rescale, exp ----
        float tm0 = accS[0][0], tm1 = accS[0][2];
#pragma unroll
        for (int j = 0; j < 16; ++j) {
            tm0 = fmaxf(tm0, fmaxf(accS[j][0], accS[j][1]));
            tm1 = fmaxf(tm1, fmaxf(accS[j][2], accS[j][3]));
        }
        tm0 = fmaxf(tm0, __shfl_xor_sync(0xffffffffu, tm0, 1));
        tm0 = fmaxf(tm0, __shfl_xor_sync(0xffffffffu, tm0, 2));
        tm1 = fmaxf(tm1, __shfl_xor_sync(0xffffffffu, tm1, 1));
        tm1 = fmaxf(tm1, __shfl_xor_sync(0xffffffffu, tm1, 2));
        const float nm0 = fmaxf(m0, tm0);
        const float nm1 = fmaxf(m1, tm1);
        const float al0 = __expf(m0 - nm0);
        const float al1 = __expf(m1 - nm1);
        m0 = nm0; m1 = nm1;

        float s0 = 0.f, s1 = 0.f;
#pragma unroll
        for (int j = 0; j < 16; ++j) {
            float p0 = __expf(accS[j][0] - nm0);
            float p1 = __expf(accS[j][1] - nm0);
            float p2 = __expf(accS[j][2] - nm1);
            float p3 = __expf(accS[j][3] - nm1);
            accS[j][0] = p0; accS[j][1] = p1; accS[j][2] = p2; accS[j][3] = p3;
            s0 += p0 + p1;
            s1 += p2 + p3;
        }
        lp0 = lp0 * al0 + s0;
        lp1 = lp1 * al1 + s1;
#pragma unroll
        for (int j = 0; j < 8; ++j) {
            accO[j][0] *= al0; accO[j][1] *= al0;
            accO[j][2] *= al1; accO[j][3] *= al1;
        }

        // ---- O += P * V (fp16 single-term) ----
#pragma unroll
        for (int kt = 0; kt < 8; ++kt) {
            u32 ah[4];
            ah[0] = h2pack(accS[2 * kt][0],     accS[2 * kt][1]);
            ah[1] = h2pack(accS[2 * kt][2],     accS[2 * kt][3]);
            ah[2] = h2pack(accS[2 * kt + 1][0], accS[2 * kt + 1][1]);
            ah[3] = h2pack(accS[2 * kt + 1][2], accS[2 * kt + 1][3]);
#pragma unroll
            for (int q = 0; q < 4; ++q) {
                u32 vh[4];
                ldsm_x4_t(vh, kvb + 2 * TILE_BYTES + kt * (16 * PITCH) + q * 32 + voff);
                mma_fp16(accO[2 * q],     ah, vh[0], vh[1]);
                mma_fp16(accO[2 * q + 1], ah, vh[2], vh[3]);
            }
        }
    }

    // ---- epilogue ----
    lp0 += __shfl_xor_sync(0xffffffffu, lp0, 1);
    lp0 += __shfl_xor_sync(0xffffffffu, lp0, 2);
    lp1 += __shfl_xor_sync(0xffffffffu, lp1, 1);
    lp1 += __shfl_xor_sync(0xffffffffu, lp1, 2);
    const float inv0 = 1.f / lp0;
    const float inv1 = 1.f / lp1;

    const int row0 = mbase + 16 * w + (lane >> 2);
    float* o0 = O + (((size_t)b * Ln + row0) * Hn + h) * Dn + (lane & 3) * 2;
    float* o1 = o0 + (size_t)8 * Hn * Dn;
#pragma unroll
    for (int j = 0; j < 8; ++j) {
        *(float2*)(o0 + 8 * j) = make_float2(accO[j][0] * inv0, accO[j][1] * inv0);
        *(float2*)(o1 + 8 * j) = make_float2(accO[j][2] * inv1, accO[j][3] * inv1);
    }
}

// ---------------- launch ----------------
extern "C" void kernel_launch(void* const* d_in, const int* in_sizes, int n_in,
                              void* d_out, int out_size) {
    const float* Q = (const float*)d_in[0];
    const float* K = (const float*)d_in[1];
    const float* V = (const float*)d_in[2];
    float* O = (float*)d_out;

    __nv_bfloat16 *qh, *ql, *kh, *kl;
    __half* vf;
    cudaGetSymbolAddress((void**)&qh, g_Qhi);
    cudaGetSymbolAddress((void**)&ql, g_Qlo);
    cudaGetSymbolAddress((void**)&kh, g_Khi);
    cudaGetSymbolAddress((void**)&kl, g_Klo);
    cudaGetSymbolAddress((void**)&vf, g_Vf);

    pack_split<<<8192, 256>>>(Q, qh, ql);
    pack_split<<<8192, 256>>>(K, kh, kl);
    pack_v<<<8192, 256>>>(V, vf);

    cudaFuncSetAttribute(fattn_mma, cudaFuncAttributeMaxDynamicSharedMemorySize, SMEM_BYTES);
    fattn_mma<<<dim3(Ln / BM, Bn * Hn), NT, SMEM_BYTES>>>(O);
}

// round 5
// speedup vs baseline: 4.0544x; 1.1220x over previous
#include <cuda_runtime.h>
#include <cuda_bf16.h>
#include <cuda_fp16.h>
#include <cstdint>

typedef unsigned int u32;

#define Bn 4
#define Ln 2048
#define Sn 2048
#define Hn 16
#define En 64
#define Dn 64
#define BM 128
#define BN 64
#define NT 256
#define NTILES (Sn / BN)

// pitch: 64 elems * 2B + 16B pad = 144 bytes (conflict-free ldmatrix)
#define PITCH 144
#define QTB (128 * PITCH)     // 18432 (Q tile: 128 rows)
#define KTB (64 * PITCH)      // 9216  (K/V tile: 64 rows)
#define OFF_QH 0
#define OFF_QL (OFF_QH + QTB)
// per KV buffer: KH(bf16), KL(bf16), VF(fp16), each KTB
#define OFF_KV(buf) (2 * QTB + (buf) * 3 * KTB)
#define SMEM_BYTES (2 * QTB + 2 * 3 * KTB)   // 92160

// ---------------- scratch ----------------
__device__ __nv_bfloat16 g_Qhi[(size_t)Bn * Hn * Ln * En];
__device__ __nv_bfloat16 g_Qlo[(size_t)Bn * Hn * Ln * En];
__device__ __nv_bfloat16 g_Khi[(size_t)Bn * Hn * Sn * En];
__device__ __nv_bfloat16 g_Klo[(size_t)Bn * Hn * Sn * En];
__device__ __half        g_Vf [(size_t)Bn * Hn * Sn * Dn];   // [b,h,s,d] fp16

// ---------------- helpers ----------------
__device__ __forceinline__ u32 smem_u32(const void* p) {
    u32 a;
    asm("{ .reg .u64 t; cvta.to.shared.u64 t, %1; cvt.u32.u64 %0, t; }" : "=r"(a) : "l"(p));
    return a;
}
__device__ __forceinline__ void cpa16(u32 dst, const void* src) {
    asm volatile("cp.async.cg.shared.global [%0], [%1], 16;" :: "r"(dst), "l"(src));
}
__device__ __forceinline__ void cpa_commit() {
    asm volatile("cp.async.commit_group;" ::: "memory");
}
template <int N>
__device__ __forceinline__ void cpa_wait() {
    asm volatile("cp.async.wait_group %0;" :: "n"(N) : "memory");
}
__device__ __forceinline__ void ldsm_x4(u32* r, u32 addr) {
    asm volatile("ldmatrix.sync.aligned.m8n8.x4.shared.b16 {%0,%1,%2,%3}, [%4];"
                 : "=r"(r[0]), "=r"(r[1]), "=r"(r[2]), "=r"(r[3]) : "r"(addr));
}
__device__ __forceinline__ void ldsm_x4_t(u32* r, u32 addr) {
    asm volatile("ldmatrix.sync.aligned.m8n8.x4.trans.shared.b16 {%0,%1,%2,%3}, [%4];"
                 : "=r"(r[0]), "=r"(r[1]), "=r"(r[2]), "=r"(r[3]) : "r"(addr));
}
__device__ __forceinline__ void mma_bf16(float* c, const u32* a, u32 b0, u32 b1) {
    asm volatile(
        "mma.sync.aligned.m16n8k16.row.col.f32.bf16.bf16.f32 "
        "{%0,%1,%2,%3}, {%4,%5,%6,%7}, {%8,%9}, {%0,%1,%2,%3};"
        : "+f"(c[0]), "+f"(c[1]), "+f"(c[2]), "+f"(c[3])
        : "r"(a[0]), "r"(a[1]), "r"(a[2]), "r"(a[3]), "r"(b0), "r"(b1));
}
__device__ __forceinline__ void mma_fp16(float* c, const u32* a, u32 b0, u32 b1) {
    asm volatile(
        "mma.sync.aligned.m16n8k16.row.col.f32.f16.f16.f32 "
        "{%0,%1,%2,%3}, {%4,%5,%6,%7}, {%8,%9}, {%0,%1,%2,%3};"
        : "+f"(c[0]), "+f"(c[1]), "+f"(c[2]), "+f"(c[3])
        : "r"(a[0]), "r"(a[1]), "r"(a[2]), "r"(a[3]), "r"(b0), "r"(b1));
}
__device__ __forceinline__ u32 h2pack(float x0, float x1) {
    __half2 h = __floats2half2_rn(x0, x1);
    return *(u32*)&h;
}

// ---------------- pre-pass: split+permute Q/K [b,x,h,e] -> [b,h,x,e] hi/lo ----------------
__global__ void pack_split(const float* __restrict__ src, __nv_bfloat16* __restrict__ hi,
                           __nv_bfloat16* __restrict__ lo) {
    int i4 = blockIdx.x * 256 + threadIdx.x;
    size_t lin = (size_t)i4 * 4;
    int e = lin & 63;
    int h = (lin >> 6) & 15;
    int l = (lin >> 10) & 2047;
    int b = (int)(lin >> 21);
    float4 v = ((const float4*)src)[i4];
    size_t dst = ((((size_t)b * Hn + h) * Ln + l) * En) + e;
    float x[4] = {v.x, v.y, v.z, v.w};
    __nv_bfloat16 hh[4], ll[4];
#pragma unroll
    for (int j = 0; j < 4; ++j) {
        hh[j] = __float2bfloat16(x[j]);
        ll[j] = __float2bfloat16(x[j] - __bfloat162float(hh[j]));
    }
    *(uint2*)(hi + dst) = *(uint2*)hh;
    *(uint2*)(lo + dst) = *(uint2*)ll;
}

// ---------------- pre-pass: V [b,s,h,d] -> [b,h,s,d] fp16 ----------------
__global__ void pack_v(const float* __restrict__ src, __half* __restrict__ dst) {
    int i4 = blockIdx.x * 256 + threadIdx.x;
    size_t lin = (size_t)i4 * 4;
    int d = lin & 63;
    int h = (lin >> 6) & 15;
    int s = (lin >> 10) & 2047;
    int b = (int)(lin >> 21);
    float4 v = ((const float4*)src)[i4];
    __half hh[4] = {__float2half_rn(v.x), __float2half_rn(v.y),
                    __float2half_rn(v.z), __float2half_rn(v.w)};
    size_t o = ((((size_t)b * Hn + h) * Sn + s) * Dn) + d;
    *(uint2*)(dst + o) = *(uint2*)hh;
}

// ---------------- main attention kernel ----------------
extern __shared__ char dsm[];

__global__ __launch_bounds__(NT, 2)
void fattn_mma(float* __restrict__ O) {
    const u32 sb = smem_u32(dsm);
    const int tid = threadIdx.x;
    const int w = tid >> 5;
    const int lane = tid & 31;

    const int bh = blockIdx.y;
    const int b = bh >> 4, h = bh & 15;
    const int mbase = blockIdx.x * BM;

    const __nv_bfloat16* gq_h = g_Qhi + ((size_t)bh * Ln + mbase) * En;
    const __nv_bfloat16* gq_l = g_Qlo + ((size_t)bh * Ln + mbase) * En;
    const __nv_bfloat16* gk_h = g_Khi + (size_t)bh * Sn * En;
    const __nv_bfloat16* gk_l = g_Klo + (size_t)bh * Sn * En;
    const __half*        gv   = g_Vf  + (size_t)bh * Sn * Dn;

    // prologue: Q (128 rows) + tile0 (64 rows each of KH/KL/V)
#pragma unroll
    for (int i = 0; i < 4; ++i) {
        int idx = tid + i * NT;                  // 0..1023
        u32 d = sb + (idx >> 3) * PITCH + (idx & 7) * 16;
        cpa16(d + OFF_QH, (const char*)gq_h + idx * 16);
        cpa16(d + OFF_QL, (const char*)gq_l + idx * 16);
    }
#pragma unroll
    for (int i = 0; i < 2; ++i) {
        int idx = tid + i * NT;                  // 0..511
        u32 d = sb + OFF_KV(0) + (idx >> 3) * PITCH + (idx & 7) * 16;
        cpa16(d + 0 * KTB, (const char*)gk_h + idx * 16);
        cpa16(d + 1 * KTB, (const char*)gk_l + idx * 16);
        cpa16(d + 2 * KTB, (const char*)gv   + idx * 16);
    }
    cpa_commit();

    const u32 koff = (lane & 7) * PITCH + (lane >> 3) * 16;
    const u32 qoff = (16 * w + ((lane >> 3) & 1) * 8 + (lane & 7)) * PITCH + (lane >> 4) * 16;
    const u32 voff = (((lane >> 3) & 1) * 8 + (lane & 7)) * PITCH + (lane >> 4) * 16;

    u32 Qh[4][4];                    // persistent hi fragments only
    float accO[8][4];
#pragma unroll
    for (int j = 0; j < 8; ++j)
#pragma unroll
        for (int i = 0; i < 4; ++i) accO[j][i] = 0.f;
    float lp0 = 0.f, lp1 = 0.f;
    float m0 = -1e30f, m1 = -1e30f;

    for (int t = 0; t < NTILES; ++t) {
        const u32 kvb = sb + OFF_KV(t & 1);

        __syncthreads();
        if (t + 1 < NTILES) {
            const u32 nb = sb + OFF_KV((t + 1) & 1);
            const size_t goffK = (size_t)(t + 1) * BN * En;
            const size_t goffV = (size_t)(t + 1) * BN * Dn;
#pragma unroll
            for (int i = 0; i < 2; ++i) {
                int idx = tid + i * NT;
                u32 d = nb + (idx >> 3) * PITCH + (idx & 7) * 16;
                cpa16(d + 0 * KTB, (const char*)(gk_h + goffK) + idx * 16);
                cpa16(d + 1 * KTB, (const char*)(gk_l + goffK) + idx * 16);
                cpa16(d + 2 * KTB, (const char*)(gv + goffV) + idx * 16);
            }
            cpa_commit();
            cpa_wait<1>();
        } else {
            cpa_wait<0>();
        }
        __syncthreads();

        if (t == 0) {
#pragma unroll
            for (int k = 0; k < 4; ++k) ldsm_x4(Qh[k], sb + OFF_QH + k * 32 + qoff);
        }
        // Q-lo fragments reloaded each tile (keeps register peak under the 2-CTA cap)
        u32 Ql[4][4];
#pragma unroll
        for (int k = 0; k < 4; ++k) ldsm_x4(Ql[k], sb + OFF_QL + k * 32 + qoff);

        // ---- S = Qhi*Khi + Qhi*Klo + Qlo*Khi (bf16 3-term) ----
        float accS[8][4];
#pragma unroll
        for (int j = 0; j < 8; ++j)
#pragma unroll
            for (int i = 0; i < 4; ++i) accS[j][i] = 0.f;

#pragma unroll
        for (int hh = 0; hh < 2; ++hh) {
#pragma unroll
            for (int j = 0; j < 8; ++j) {
                u32 kh[4], kl[4];
                ldsm_x4(kh, kvb + 0 * KTB + j * (8 * PITCH) + hh * 64 + koff);
                ldsm_x4(kl, kvb + 1 * KTB + j * (8 * PITCH) + hh * 64 + koff);
                mma_bf16(accS[j], Qh[2 * hh], kh[0], kh[1]);
                mma_bf16(accS[j], Qh[2 * hh], kl[0], kl[1]);
                mma_bf16(accS[j], Ql[2 * hh], kh[0], kh[1]);
                mma_bf16(accS[j], Qh[2 * hh + 1], kh[2], kh[3]);
                mma_bf16(accS[j], Qh[2 * hh + 1], kl[2], kl[3]);
                mma_bf16(accS[j], Ql[2 * hh + 1], kh[2], kh[3]);
            }
        }

        // ---- online softmax ----
        float tm0 = accS[0][0], tm1 = accS[0][2];
#pragma unroll
        for (int j = 0; j < 8; ++j) {
            tm0 = fmaxf(tm0, fmaxf(accS[j][0], accS[j][1]));
            tm1 = fmaxf(tm1, fmaxf(accS[j][2], accS[j][3]));
        }
        tm0 = fmaxf(tm0, __shfl_xor_sync(0xffffffffu, tm0, 1));
        tm0 = fmaxf(tm0, __shfl_xor_sync(0xffffffffu, tm0, 2));
        tm1 = fmaxf(tm1, __shfl_xor_sync(0xffffffffu, tm1, 1));
        tm1 = fmaxf(tm1, __shfl_xor_sync(0xffffffffu, tm1, 2));
        const float nm0 = fmaxf(m0, tm0);
        const float nm1 = fmaxf(m1, tm1);
        const float al0 = __expf(m0 - nm0);
        const float al1 = __expf(m1 - nm1);
        m0 = nm0; m1 = nm1;

        float s0 = 0.f, s1 = 0.f;
#pragma unroll
        for (int j = 0; j < 8; ++j) {
            float p0 = __expf(accS[j][0] - nm0);
            float p1 = __expf(accS[j][1] - nm0);
            float p2 = __expf(accS[j][2] - nm1);
            float p3 = __expf(accS[j][3] - nm1);
            accS[j][0] = p0; accS[j][1] = p1; accS[j][2] = p2; accS[j][3] = p3;
            s0 += p0 + p1;
            s1 += p2 + p3;
        }
        lp0 = lp0 * al0 + s0;
        lp1 = lp1 * al1 + s1;
#pragma unroll
        for (int j = 0; j < 8; ++j) {
            accO[j][0] *= al0; accO[j][1] *= al0;
            accO[j][2] *= al1; accO[j][3] *= al1;
        }

        // ---- O += P * V (fp16 single-term) ----
#pragma unroll
        for (int kt = 0; kt < 4; ++kt) {
            u32 ah[4];
            ah[0] = h2pack(accS[2 * kt][0],     accS[2 * kt][1]);
            ah[1] = h2pack(accS[2 * kt][2],     accS[2 * kt][3]);
            ah[2] = h2pack(accS[2 * kt + 1][0], accS[2 * kt + 1][1]);
            ah[3] = h2pack(accS[2 * kt + 1][2], accS[2 * kt + 1][3]);
#pragma unroll
            for (int q = 0; q < 4; ++q) {
                u32 vh[4];
                ldsm_x4_t(vh, kvb + 2 * KTB + kt * (16 * PITCH) + q * 32 + voff);
                mma_fp16(accO[2 * q],     ah, vh[0], vh[1]);
                mma_fp16(accO[2 * q + 1], ah, vh[2], vh[3]);
            }
        }
    }

    // ---- epilogue ----
    lp0 += __shfl_xor_sync(0xffffffffu, lp0, 1);
    lp0 += __shfl_xor_sync(0xffffffffu, lp0, 2);
    lp1 += __shfl_xor_sync(0xffffffffu, lp1, 1);
    lp1 += __shfl_xor_sync(0xffffffffu, lp1, 2);
    const float inv0 = 1.f / lp0;
    const float inv1 = 1.f / lp1;

    const int row0 = mbase + 16 * w + (lane >> 2);
    float* o0 = O + (((size_t)b * Ln + row0) * Hn + h) * Dn + (lane & 3) * 2;
    float* o1 = o0 + (size_t)8 * Hn * Dn;
#pragma unroll
    for (int j = 0; j < 8; ++j) {
        *(float2*)(o0 + 8 * j) = make_float2(accO[j][0] * inv0, accO[j][1] * inv0);
        *(float2*)(o1 + 8 * j) = make_float2(accO[j][2] * inv1, accO[j][3] * inv1);
    }
}

// ---------------- launch ----------------
extern "C" void kernel_launch(void* const* d_in, const int* in_sizes, int n_in,
                              void* d_out, int out_size) {
    const float* Q = (const float*)d_in[0];
    const float* K = (const float*)d_in[1];
    const float* V = (const float*)d_in[2];
    float* O = (float*)d_out;

    __nv_bfloat16 *qh, *ql, *kh, *kl;
    __half* vf;
    cudaGetSymbolAddress((void**)&qh, g_Qhi);
    cudaGetSymbolAddress((void**)&ql, g_Qlo);
    cudaGetSymbolAddress((void**)&kh, g_Khi);
    cudaGetSymbolAddress((void**)&kl, g_Klo);
    cudaGetSymbolAddress((void**)&vf, g_Vf);

    pack_split<<<8192, 256>>>(Q, qh, ql);
    pack_split<<<8192, 256>>>(K, kh, kl);
    pack_v<<<8192, 256>>>(V, vf);

    cudaFuncSetAttribute(fattn_mma, cudaFuncAttributeMaxDynamicSharedMemorySize, SMEM_BYTES);
    fattn_mma<<<dim3(Ln / BM, Bn * Hn), NT, SMEM_BYTES>>>(O);
}

// round 6
// speedup vs baseline: 5.7899x; 1.4281x over previous
#include <cuda_runtime.h>
#include <cuda_fp16.h>
#include <cstdint>

typedef unsigned int u32;

#define Bn 4
#define Ln 2048
#define Sn 2048
#define Hn 16
#define En 64
#define Dn 64
#define BM 128
#define BN 64
#define NT 256
#define NTILES (Sn / BN)
#define L2E 1.44269504f
#define ONE2 0x3C003C00u

// pitch: 64 elems * 2B + 16B pad = 144 bytes (conflict-free ldmatrix)
#define PITCH 144
#define QTB (128 * PITCH)     // 18432 (Q tile: 128 rows)
#define KTB (64 * PITCH)      // 9216  (K/V tile: 64 rows)
#define OFF_QH 0
#define OFF_QL (OFF_QH + QTB)
// per KV buffer: K(fp16), V(fp16)
#define OFF_KV(buf) (2 * QTB + (buf) * 2 * KTB)
#define SMEM_BYTES (2 * QTB + 2 * 2 * KTB)   // 73728

// ---------------- scratch (fp16, repacked [b,h,s,e]) ----------------
__device__ __half g_Qh[(size_t)Bn * Hn * Ln * En];
__device__ __half g_Ql[(size_t)Bn * Hn * Ln * En];
__device__ __half g_Kf[(size_t)Bn * Hn * Sn * En];
__device__ __half g_Vf[(size_t)Bn * Hn * Sn * Dn];

// ---------------- helpers ----------------
__device__ __forceinline__ u32 smem_u32(const void* p) {
    u32 a;
    asm("{ .reg .u64 t; cvta.to.shared.u64 t, %1; cvt.u32.u64 %0, t; }" : "=r"(a) : "l"(p));
    return a;
}
__device__ __forceinline__ void cpa16(u32 dst, const void* src) {
    asm volatile("cp.async.cg.shared.global [%0], [%1], 16;" :: "r"(dst), "l"(src));
}
__device__ __forceinline__ void cpa_commit() {
    asm volatile("cp.async.commit_group;" ::: "memory");
}
template <int N>
__device__ __forceinline__ void cpa_wait() {
    asm volatile("cp.async.wait_group %0;" :: "n"(N) : "memory");
}
__device__ __forceinline__ void ldsm_x4(u32* r, u32 addr) {
    asm volatile("ldmatrix.sync.aligned.m8n8.x4.shared.b16 {%0,%1,%2,%3}, [%4];"
                 : "=r"(r[0]), "=r"(r[1]), "=r"(r[2]), "=r"(r[3]) : "r"(addr));
}
__device__ __forceinline__ void ldsm_x4_t(u32* r, u32 addr) {
    asm volatile("ldmatrix.sync.aligned.m8n8.x4.trans.shared.b16 {%0,%1,%2,%3}, [%4];"
                 : "=r"(r[0]), "=r"(r[1]), "=r"(r[2]), "=r"(r[3]) : "r"(addr));
}
__device__ __forceinline__ void mma_fp16(float* c, const u32* a, u32 b0, u32 b1) {
    asm volatile(
        "mma.sync.aligned.m16n8k16.row.col.f32.f16.f16.f32 "
        "{%0,%1,%2,%3}, {%4,%5,%6,%7}, {%8,%9}, {%0,%1,%2,%3};"
        : "+f"(c[0]), "+f"(c[1]), "+f"(c[2]), "+f"(c[3])
        : "r"(a[0]), "r"(a[1]), "r"(a[2]), "r"(a[3]), "r"(b0), "r"(b1));
}
__device__ __forceinline__ u32 cvt_f16x2(float lo, float hi) {
    u32 d;
    asm("cvt.rn.f16x2.f32 %0, %1, %2;" : "=r"(d) : "f"(hi), "f"(lo));
    return d;
}
__device__ __forceinline__ u32 ex2_f16x2(u32 x) {
    u32 d;
    asm("ex2.approx.f16x2 %0, %1;" : "=r"(d) : "r"(x));
    return d;
}

// ---------------- pre-pass: Q split+permute [b,l,h,e] -> [b,h,l,e] fp16 hi/lo ----------------
__global__ void pack_q(const float* __restrict__ src, __half* __restrict__ hi,
                       __half* __restrict__ lo) {
    int i4 = blockIdx.x * 256 + threadIdx.x;
    size_t lin = (size_t)i4 * 4;
    int e = lin & 63;
    int h = (lin >> 6) & 15;
    int l = (lin >> 10) & 2047;
    int b = (int)(lin >> 21);
    float4 v = ((const float4*)src)[i4];
    size_t dst = ((((size_t)b * Hn + h) * Ln + l) * En) + e;
    float x[4] = {v.x, v.y, v.z, v.w};
    __half hh[4], ll[4];
#pragma unroll
    for (int j = 0; j < 4; ++j) {
        hh[j] = __float2half_rn(x[j]);
        ll[j] = __float2half_rn(x[j] - __half2float(hh[j]));
    }
    *(uint2*)(hi + dst) = *(uint2*)hh;
    *(uint2*)(lo + dst) = *(uint2*)ll;
}

// ---------------- pre-pass: K/V [b,s,h,e] -> [b,h,s,e] fp16 ----------------
__global__ void pack_half(const float* __restrict__ src, __half* __restrict__ dst) {
    int i4 = blockIdx.x * 256 + threadIdx.x;
    size_t lin = (size_t)i4 * 4;
    int d = lin & 63;
    int h = (lin >> 6) & 15;
    int s = (lin >> 10) & 2047;
    int b = (int)(lin >> 21);
    float4 v = ((const float4*)src)[i4];
    __half hh[4] = {__float2half_rn(v.x), __float2half_rn(v.y),
                    __float2half_rn(v.z), __float2half_rn(v.w)};
    size_t o = ((((size_t)b * Hn + h) * Sn + s) * Dn) + d;
    *(uint2*)(dst + o) = *(uint2*)hh;
}

// ---------------- main attention kernel ----------------
extern __shared__ char dsm[];

__global__ __launch_bounds__(NT, 2)
void fattn_mma(float* __restrict__ O) {
    const u32 sb = smem_u32(dsm);
    const int tid = threadIdx.x;
    const int w = tid >> 5;
    const int lane = tid & 31;

    const int bh = blockIdx.y;
    const int b = bh >> 4, h = bh & 15;
    const int mbase = blockIdx.x * BM;

    const __half* gq_h = g_Qh + ((size_t)bh * Ln + mbase) * En;
    const __half* gq_l = g_Ql + ((size_t)bh * Ln + mbase) * En;
    const __half* gk   = g_Kf + (size_t)bh * Sn * En;
    const __half* gv   = g_Vf + (size_t)bh * Sn * Dn;

    // prologue group 0: Q (128 rows hi/lo) + tile0 K,V
#pragma unroll
    for (int i = 0; i < 4; ++i) {
        int idx = tid + i * NT;                  // 0..1023
        u32 d = sb + (idx >> 3) * PITCH + (idx & 7) * 16;
        cpa16(d + OFF_QH, (const char*)gq_h + idx * 16);
        cpa16(d + OFF_QL, (const char*)gq_l + idx * 16);
    }
#pragma unroll
    for (int i = 0; i < 2; ++i) {
        int idx = tid + i * NT;                  // 0..511
        u32 d = sb + OFF_KV(0) + (idx >> 3) * PITCH + (idx & 7) * 16;
        cpa16(d + 0 * KTB, (const char*)gk + idx * 16);
        cpa16(d + 1 * KTB, (const char*)gv + idx * 16);
    }
    cpa_commit();

    const u32 koff = (lane & 7) * PITCH + (lane >> 3) * 16;
    const u32 qoff = (16 * w + ((lane >> 3) & 1) * 8 + (lane & 7)) * PITCH + (lane >> 4) * 16;
    const u32 voff = (((lane >> 3) & 1) * 8 + (lane & 7)) * PITCH + (lane >> 4) * 16;

    u32 Qh[4][4];
    float accO[8][4];
#pragma unroll
    for (int j = 0; j < 8; ++j)
#pragma unroll
        for (int i = 0; i < 4; ++i) accO[j][i] = 0.f;
    float accL[4] = {0.f, 0.f, 0.f, 0.f};
    float m0 = -1e30f, m1 = -1e30f;

    for (int t = 0; t < NTILES; ++t) {
        const u32 kvb = sb + OFF_KV(t & 1);

        cpa_wait<0>();
        __syncthreads();      // single barrier per tile: data visible + prev buffer free

        if (t + 1 < NTILES) {
            const u32 nb = sb + OFF_KV((t + 1) & 1);
            const size_t goffK = (size_t)(t + 1) * BN * En;
            const size_t goffV = (size_t)(t + 1) * BN * Dn;
#pragma unroll
            for (int i = 0; i < 2; ++i) {
                int idx = tid + i * NT;
                u32 d = nb + (idx >> 3) * PITCH + (idx & 7) * 16;
                cpa16(d + 0 * KTB, (const char*)(gk + goffK) + idx * 16);
                cpa16(d + 1 * KTB, (const char*)(gv + goffV) + idx * 16);
            }
            cpa_commit();
        }

        if (t == 0) {
#pragma unroll
            for (int k = 0; k < 4; ++k) ldsm_x4(Qh[k], sb + OFF_QH + k * 32 + qoff);
        }
        u32 Ql[4][4];
#pragma unroll
        for (int k = 0; k < 4; ++k) ldsm_x4(Ql[k], sb + OFF_QL + k * 32 + qoff);

        // ---- S = Qh*K + Ql*K (fp16 2-term) ----
        float accS[8][4];
#pragma unroll
        for (int j = 0; j < 8; ++j)
#pragma unroll
            for (int i = 0; i < 4; ++i) accS[j][i] = 0.f;

#pragma unroll
        for (int hh = 0; hh < 2; ++hh) {
#pragma unroll
            for (int j = 0; j < 8; ++j) {
                u32 kh[4];
                ldsm_x4(kh, kvb + 0 * KTB + j * (8 * PITCH) + hh * 64 + koff);
                mma_fp16(accS[j], Qh[2 * hh], kh[0], kh[1]);
                mma_fp16(accS[j], Ql[2 * hh], kh[0], kh[1]);
                mma_fp16(accS[j], Qh[2 * hh + 1], kh[2], kh[3]);
                mma_fp16(accS[j], Ql[2 * hh + 1], kh[2], kh[3]);
            }
        }

        // ---- online softmax: tile row max, rescale ----
        float tm0 = accS[0][0], tm1 = accS[0][2];
#pragma unroll
        for (int j = 0; j < 8; ++j) {
            tm0 = fmaxf(tm0, fmaxf(accS[j][0], accS[j][1]));
            tm1 = fmaxf(tm1, fmaxf(accS[j][2], accS[j][3]));
        }
        tm0 = fmaxf(tm0, __shfl_xor_sync(0xffffffffu, tm0, 1));
        tm0 = fmaxf(tm0, __shfl_xor_sync(0xffffffffu, tm0, 2));
        tm1 = fmaxf(tm1, __shfl_xor_sync(0xffffffffu, tm1, 1));
        tm1 = fmaxf(tm1, __shfl_xor_sync(0xffffffffu, tm1, 2));
        const float nm0 = fmaxf(m0, tm0);
        const float nm1 = fmaxf(m1, tm1);
        const float al0 = __expf(m0 - nm0);
        const float al1 = __expf(m1 - nm1);
        m0 = nm0; m1 = nm1;
        const float c0 = -nm0 * L2E;   // exp(x-nm) = 2^(x*L2E + c)
        const float c1 = -nm1 * L2E;

#pragma unroll
        for (int j = 0; j < 8; ++j) {
            accO[j][0] *= al0; accO[j][1] *= al0;
            accO[j][2] *= al1; accO[j][3] *= al1;
        }
        accL[0] *= al0;
        accL[2] *= al1;

        // ---- per kt: fp16x2 exp -> PV MMA + L MMA ----
#pragma unroll
        for (int kt = 0; kt < 4; ++kt) {
            u32 ah[4];
            ah[0] = ex2_f16x2(cvt_f16x2(fmaf(accS[2 * kt][0], L2E, c0),
                                        fmaf(accS[2 * kt][1], L2E, c0)));
            ah[1] = ex2_f16x2(cvt_f16x2(fmaf(accS[2 * kt][2], L2E, c1),
                                        fmaf(accS[2 * kt][3], L2E, c1)));
            ah[2] = ex2_f16x2(cvt_f16x2(fmaf(accS[2 * kt + 1][0], L2E, c0),
                                        fmaf(accS[2 * kt + 1][1], L2E, c0)));
            ah[3] = ex2_f16x2(cvt_f16x2(fmaf(accS[2 * kt + 1][2], L2E, c1),
                                        fmaf(accS[2 * kt + 1][3], L2E, c1)));
#pragma unroll
            for (int q = 0; q < 4; ++q) {
                u32 vh[4];
                ldsm_x4_t(vh, kvb + 1 * KTB + kt * (16 * PITCH) + q * 32 + voff);
                mma_fp16(accO[2 * q],     ah, vh[0], vh[1]);
                mma_fp16(accO[2 * q + 1], ah, vh[2], vh[3]);
            }
            mma_fp16(accL, ah, ONE2, ONE2);   // row sums in fp32 via tensor pipe
        }
    }

    // ---- epilogue: l comes exact from the ones-MMA (no shuffles) ----
    const float inv0 = 1.f / accL[0];
    const float inv1 = 1.f / accL[2];

    const int row0 = mbase + 16 * w + (lane >> 2);
    float* o0 = O + (((size_t)b * Ln + row0) * Hn + h) * Dn + (lane & 3) * 2;
    float* o1 = o0 + (size_t)8 * Hn * Dn;
#pragma unroll
    for (int j = 0; j < 8; ++j) {
        *(float2*)(o0 + 8 * j) = make_float2(accO[j][0] * inv0, accO[j][1] * inv0);
        *(float2*)(o1 + 8 * j) = make_float2(accO[j][2] * inv1, accO[j][3] * inv1);
    }
}

// ---------------- launch ----------------
extern "C" void kernel_launch(void* const* d_in, const int* in_sizes, int n_in,
                              void* d_out, int out_size) {
    const float* Q = (const float*)d_in[0];
    const float* K = (const float*)d_in[1];
    const float* V = (const float*)d_in[2];
    float* O = (float*)d_out;

    __half *qh, *ql, *kf, *vf;
    cudaGetSymbolAddress((void**)&qh, g_Qh);
    cudaGetSymbolAddress((void**)&ql, g_Ql);
    cudaGetSymbolAddress((void**)&kf, g_Kf);
    cudaGetSymbolAddress((void**)&vf, g_Vf);

    pack_q<<<8192, 256>>>(Q, qh, ql);
    pack_half<<<8192, 256>>>(K, kf);
    pack_half<<<8192, 256>>>(V, vf);

    cudaFuncSetAttribute(fattn_mma, cudaFuncAttributeMaxDynamicSharedMemorySize, SMEM_BYTES);
    fattn_mma<<<dim3(Ln / BM, Bn * Hn), NT, SMEM_BYTES>>>(O);
}

// round 7
// speedup vs baseline: 5.9235x; 1.0231x over previous
#include <cuda_runtime.h>
#include <cuda_fp16.h>
#include <cstdint>

typedef unsigned int u32;

#define Bn 4
#define Ln 2048
#define Sn 2048
#define Hn 16
#define En 64
#define Dn 64
#define BM 128
#define BN 64
#define NT 256
#define NTILES (Sn / BN)
#define L2E 1.44269504f
#define ONE2 0x3C003C00u

// pitch: 64 elems * 2B + 16B pad = 144 bytes (conflict-free ldmatrix)
#define PITCH 144
#define QTB (128 * PITCH)     // 18432 (Q tile: 128 rows)
#define KTB (64 * PITCH)      // 9216  (K/V tile: 64 rows)
#define OFF_QH 0
#define OFF_QL (OFF_QH + QTB)
#define OFF_KV(buf) (2 * QTB + (buf) * 2 * KTB)
#define SMEM_BYTES (2 * QTB + 2 * 2 * KTB)   // 73728

// ---------------- scratch (fp16, repacked [b,h,s,e]) ----------------
__device__ __half g_Qh[(size_t)Bn * Hn * Ln * En];
__device__ __half g_Ql[(size_t)Bn * Hn * Ln * En];
__device__ __half g_Kf[(size_t)Bn * Hn * Sn * En];
__device__ __half g_Vf[(size_t)Bn * Hn * Sn * Dn];

// ---------------- helpers ----------------
__device__ __forceinline__ u32 smem_u32(const void* p) {
    u32 a;
    asm("{ .reg .u64 t; cvta.to.shared.u64 t, %1; cvt.u32.u64 %0, t; }" : "=r"(a) : "l"(p));
    return a;
}
__device__ __forceinline__ void cpa16(u32 dst, const void* src) {
    asm volatile("cp.async.cg.shared.global [%0], [%1], 16;" :: "r"(dst), "l"(src));
}
__device__ __forceinline__ void cpa_commit() {
    asm volatile("cp.async.commit_group;" ::: "memory");
}
template <int N>
__device__ __forceinline__ void cpa_wait() {
    asm volatile("cp.async.wait_group %0;" :: "n"(N) : "memory");
}
__device__ __forceinline__ void ldsm_x4(u32* r, u32 addr) {
    asm volatile("ldmatrix.sync.aligned.m8n8.x4.shared.b16 {%0,%1,%2,%3}, [%4];"
                 : "=r"(r[0]), "=r"(r[1]), "=r"(r[2]), "=r"(r[3]) : "r"(addr));
}
__device__ __forceinline__ void ldsm_x4_t(u32* r, u32 addr) {
    asm volatile("ldmatrix.sync.aligned.m8n8.x4.trans.shared.b16 {%0,%1,%2,%3}, [%4];"
                 : "=r"(r[0]), "=r"(r[1]), "=r"(r[2]), "=r"(r[3]) : "r"(addr));
}
__device__ __forceinline__ void mma_fp16(float* c, const u32* a, u32 b0, u32 b1) {
    asm volatile(
        "mma.sync.aligned.m16n8k16.row.col.f32.f16.f16.f32 "
        "{%0,%1,%2,%3}, {%4,%5,%6,%7}, {%8,%9}, {%0,%1,%2,%3};"
        : "+f"(c[0]), "+f"(c[1]), "+f"(c[2]), "+f"(c[3])
        : "r"(a[0]), "r"(a[1]), "r"(a[2]), "r"(a[3]), "r"(b0), "r"(b1));
}
__device__ __forceinline__ u32 cvt_f16x2(float lo, float hi) {
    u32 d;
    asm("cvt.rn.f16x2.f32 %0, %1, %2;" : "=r"(d) : "f"(hi), "f"(lo));
    return d;
}
__device__ __forceinline__ u32 ex2_f16x2(u32 x) {
    u32 d;
    asm("ex2.approx.f16x2 %0, %1;" : "=r"(d) : "r"(x));
    return d;
}

// ---------------- fused pre-pass: one kernel, 3 regions ----------------
// y=0: Q -> g_Qh/g_Ql (fp16 hi/lo split), y=1: K -> g_Kf, y=2: V -> g_Vf
// all with [b,x,h,e] -> [b,h,x,e] permute.
__global__ void pack_all(const float* __restrict__ Q, const float* __restrict__ K,
                         const float* __restrict__ V) {
    const int region = blockIdx.y;
    const int i4 = blockIdx.x * 256 + threadIdx.x;
    const size_t lin = (size_t)i4 * 4;
    const int e = lin & 63;
    const int h = (lin >> 6) & 15;
    const int x = (lin >> 10) & 2047;
    const int b = (int)(lin >> 21);
    const size_t dst = ((((size_t)b * Hn + h) * Ln + x) * En) + e;

    if (region == 0) {
        float4 v = ((const float4*)Q)[i4];
        float xx[4] = {v.x, v.y, v.z, v.w};
        __half hh[4], ll[4];
#pragma unroll
        for (int j = 0; j < 4; ++j) {
            hh[j] = __float2half_rn(xx[j]);
            ll[j] = __float2half_rn(xx[j] - __half2float(hh[j]));
        }
        *(uint2*)(g_Qh + dst) = *(uint2*)hh;
        *(uint2*)(g_Ql + dst) = *(uint2*)ll;
    } else {
        const float* src = (region == 1) ? K : V;
        __half* out = (region == 1) ? g_Kf : g_Vf;
        float4 v = ((const float4*)src)[i4];
        __half hh[4] = {__float2half_rn(v.x), __float2half_rn(v.y),
                        __float2half_rn(v.z), __float2half_rn(v.w)};
        *(uint2*)(out + dst) = *(uint2*)hh;
    }
}

// ---------------- main attention kernel ----------------
extern __shared__ char dsm[];

__global__ __launch_bounds__(NT, 2)
void fattn_mma(float* __restrict__ O) {
    const u32 sb = smem_u32(dsm);
    const int tid = threadIdx.x;
    const int w = tid >> 5;
    const int lane = tid & 31;

    const int bh = blockIdx.y;
    const int b = bh >> 4, h = bh & 15;
    const int mbase = blockIdx.x * BM;

    const __half* gq_h = g_Qh + ((size_t)bh * Ln + mbase) * En;
    const __half* gq_l = g_Ql + ((size_t)bh * Ln + mbase) * En;
    const __half* gk   = g_Kf + (size_t)bh * Sn * En;
    const __half* gv   = g_Vf + (size_t)bh * Sn * Dn;

    // prologue group 0: Q (128 rows hi/lo) + tile0 K,V
#pragma unroll
    for (int i = 0; i < 4; ++i) {
        int idx = tid + i * NT;
        u32 d = sb + (idx >> 3) * PITCH + (idx & 7) * 16;
        cpa16(d + OFF_QH, (const char*)gq_h + idx * 16);
        cpa16(d + OFF_QL, (const char*)gq_l + idx * 16);
    }
#pragma unroll
    for (int i = 0; i < 2; ++i) {
        int idx = tid + i * NT;
        u32 d = sb + OFF_KV(0) + (idx >> 3) * PITCH + (idx & 7) * 16;
        cpa16(d + 0 * KTB, (const char*)gk + idx * 16);
        cpa16(d + 1 * KTB, (const char*)gv + idx * 16);
    }
    cpa_commit();

    const u32 koff = (lane & 7) * PITCH + (lane >> 3) * 16;
    const u32 qoff = (16 * w + ((lane >> 3) & 1) * 8 + (lane & 7)) * PITCH + (lane >> 4) * 16;
    const u32 voff = (((lane >> 3) & 1) * 8 + (lane & 7)) * PITCH + (lane >> 4) * 16;

    u32 Qh[4][4], Ql[4][4];            // persistent (tile-invariant)
    float accO[8][4];
#pragma unroll
    for (int j = 0; j < 8; ++j)
#pragma unroll
        for (int i = 0; i < 4; ++i) accO[j][i] = 0.f;
    float accL[4] = {0.f, 0.f, 0.f, 0.f};
    float m0 = -1e30f, m1 = -1e30f;

    for (int t = 0; t < NTILES; ++t) {
        const u32 kvb = sb + OFF_KV(t & 1);

        cpa_wait<0>();
        __syncthreads();      // data visible + prev buffer free

        if (t + 1 < NTILES) {
            const u32 nb = sb + OFF_KV((t + 1) & 1);
            const size_t goffK = (size_t)(t + 1) * BN * En;
            const size_t goffV = (size_t)(t + 1) * BN * Dn;
#pragma unroll
            for (int i = 0; i < 2; ++i) {
                int idx = tid + i * NT;
                u32 d = nb + (idx >> 3) * PITCH + (idx & 7) * 16;
                cpa16(d + 0 * KTB, (const char*)(gk + goffK) + idx * 16);
                cpa16(d + 1 * KTB, (const char*)(gv + goffV) + idx * 16);
            }
            cpa_commit();
        }

        if (t == 0) {
#pragma unroll
            for (int k = 0; k < 4; ++k) {
                ldsm_x4(Qh[k], sb + OFF_QH + k * 32 + qoff);
                ldsm_x4(Ql[k], sb + OFF_QL + k * 32 + qoff);
            }
        }

        // ---- S = Qh*K + Ql*K (fp16 2-term), software-pipelined K fragments ----
        float accS[8][4];
#pragma unroll
        for (int j = 0; j < 8; ++j)
#pragma unroll
            for (int i = 0; i < 4; ++i) accS[j][i] = 0.f;

        {
            const u32 kbase = kvb + koff;
            u32 kc[4], kn[4];
            ldsm_x4(kc, kbase);
#pragma unroll
            for (int idx = 0; idx < 16; ++idx) {
                const int hh = idx >> 3, j = idx & 7;
                if (idx < 15) {
                    const int n = idx + 1;
                    ldsm_x4(kn, kbase + (n & 7) * (8 * PITCH) + (n >> 3) * 64);
                }
                mma_fp16(accS[j], Qh[2 * hh],     kc[0], kc[1]);
                mma_fp16(accS[j], Ql[2 * hh],     kc[0], kc[1]);
                mma_fp16(accS[j], Qh[2 * hh + 1], kc[2], kc[3]);
                mma_fp16(accS[j], Ql[2 * hh + 1], kc[2], kc[3]);
                kc[0] = kn[0]; kc[1] = kn[1]; kc[2] = kn[2]; kc[3] = kn[3];
            }
        }

        // ---- online softmax: tile row max, rescale ----
        float tm0 = accS[0][0], tm1 = accS[0][2];
#pragma unroll
        for (int j = 0; j < 8; ++j) {
            tm0 = fmaxf(tm0, fmaxf(accS[j][0], accS[j][1]));
            tm1 = fmaxf(tm1, fmaxf(accS[j][2], accS[j][3]));
        }
        tm0 = fmaxf(tm0, __shfl_xor_sync(0xffffffffu, tm0, 1));
        tm1 = fmaxf(tm1, __shfl_xor_sync(0xffffffffu, tm1, 1));
        tm0 = fmaxf(tm0, __shfl_xor_sync(0xffffffffu, tm0, 2));
        tm1 = fmaxf(tm1, __shfl_xor_sync(0xffffffffu, tm1, 2));

        const u32 vbase = kvb + 1 * KTB + voff;
        u32 vc[4], vn[4];
        ldsm_x4_t(vc, vbase);    // first V fragment: overlaps the exp/rescale ALU below

        const float nm0 = fmaxf(m0, tm0);
        const float nm1 = fmaxf(m1, tm1);
        const float al0 = __expf(m0 - nm0);
        const float al1 = __expf(m1 - nm1);
        m0 = nm0; m1 = nm1;
        const float c0 = -nm0 * L2E;
        const float c1 = -nm1 * L2E;

#pragma unroll
        for (int j = 0; j < 8; ++j) {
            accO[j][0] *= al0; accO[j][1] *= al0;
            accO[j][2] *= al1; accO[j][3] *= al1;
        }
        accL[0] *= al0;
        accL[2] *= al1;

        // ---- PV: per kt convert to fp16 P, then MMAs with pipelined V fragments ----
#pragma unroll
        for (int idx = 0; idx < 16; ++idx) {
            const int kt = idx >> 2, q = idx & 3;
            u32 ah[4];
            if (q == 0) {
                ah[0] = ex2_f16x2(cvt_f16x2(fmaf(accS[2 * kt][0], L2E, c0),
                                            fmaf(accS[2 * kt][1], L2E, c0)));
                ah[1] = ex2_f16x2(cvt_f16x2(fmaf(accS[2 * kt][2], L2E, c1),
                                            fmaf(accS[2 * kt][3], L2E, c1)));
                ah[2] = ex2_f16x2(cvt_f16x2(fmaf(accS[2 * kt + 1][0], L2E, c0),
                                            fmaf(accS[2 * kt + 1][1], L2E, c0)));
                ah[3] = ex2_f16x2(cvt_f16x2(fmaf(accS[2 * kt + 1][2], L2E, c1),
                                            fmaf(accS[2 * kt + 1][3], L2E, c1)));
                // stash in accS slots (dead after conversion) so ah persists across q
                accS[2 * kt][0] = __uint_as_float(ah[0]);
                accS[2 * kt][1] = __uint_as_float(ah[1]);
                accS[2 * kt][2] = __uint_as_float(ah[2]);
                accS[2 * kt][3] = __uint_as_float(ah[3]);
                mma_fp16(accL, ah, ONE2, ONE2);   // row sums via tensor pipe
            } else {
                ah[0] = __float_as_uint(accS[2 * kt][0]);
                ah[1] = __float_as_uint(accS[2 * kt][1]);
                ah[2] = __float_as_uint(accS[2 * kt][2]);
                ah[3] = __float_as_uint(accS[2 * kt][3]);
            }
            if (idx < 15) {
                const int n = idx + 1;
                ldsm_x4_t(vn, vbase + (n >> 2) * (16 * PITCH) + (n & 3) * 32);
            }
            mma_fp16(accO[2 * q],     ah, vc[0], vc[1]);
            mma_fp16(accO[2 * q + 1], ah, vc[2], vc[3]);
            vc[0] = vn[0]; vc[1] = vn[1]; vc[2] = vn[2]; vc[3] = vn[3];
        }
    }

    // ---- epilogue: l exact from the ones-MMA ----
    const float inv0 = 1.f / accL[0];
    const float inv1 = 1.f / accL[2];

    const int row0 = mbase + 16 * w + (lane >> 2);
    float* o0 = O + (((size_t)b * Ln + row0) * Hn + h) * Dn + (lane & 3) * 2;
    float* o1 = o0 + (size_t)8 * Hn * Dn;
#pragma unroll
    for (int j = 0; j < 8; ++j) {
        *(float2*)(o0 + 8 * j) = make_float2(accO[j][0] * inv0, accO[j][1] * inv0);
        *(float2*)(o1 + 8 * j) = make_float2(accO[j][2] * inv1, accO[j][3] * inv1);
    }
}

// ---------------- launch ----------------
extern "C" void kernel_launch(void* const* d_in, const int* in_sizes, int n_in,
                              void* d_out, int out_size) {
    const float* Q = (const float*)d_in[0];
    const float* K = (const float*)d_in[1];
    const float* V = (const float*)d_in[2];
    float* O = (float*)d_out;

    pack_all<<<dim3(8192, 3), 256>>>(Q, K, V);

    cudaFuncSetAttribute(fattn_mma, cudaFuncAttributeMaxDynamicSharedMemorySize, SMEM_BYTES);
    fattn_mma<<<dim3(Ln / BM, Bn * Hn), NT, SMEM_BYTES>>>(O);
}